// round 12
// baseline (speedup 1.0000x reference)
#include <cuda_runtime.h>
#include <math.h>
#include <stdint.h>
#include <stddef.h>

#define BB   32
#define TT   4096
#define TP   1024
#define DD   64
#define HH   512
#define G4   2048
#define OUTD 6
#define NCTA 128

// ---------------- f32x2 helpers ----------------
__device__ __forceinline__ unsigned long long ffma2(unsigned long long a,
                                                    unsigned long long b,
                                                    unsigned long long c) {
    unsigned long long d;
    asm("fma.rn.f32x2 %0, %1, %2, %3;" : "=l"(d) : "l"(a), "l"(b), "l"(c));
    return d;
}
__device__ __forceinline__ unsigned long long pack2(float lo, float hi) {
    unsigned long long r;
    asm("mov.b64 %0, {%1, %2};" : "=l"(r) : "f"(lo), "f"(hi));
    return r;
}
__device__ __forceinline__ float2 unpack2(unsigned long long v) {
    float2 r;
    asm("mov.b64 {%0, %1}, %2;" : "=f"(r.x), "=f"(r.y) : "l"(v));
    return r;
}
__device__ __forceinline__ float fsigmoid(float x) {
    return __fdividef(1.f, 1.f + __expf(-x));
}
__device__ __forceinline__ float ftanh(float x) {
    return 1.f - __fdividef(2.f, __expf(2.f * x) + 1.f);
}

// ---------------- scratch ----------------
static __device__ float d_sig[BB * TT];
static __device__ float d_c1 [BB * 64 * 2048];
static __device__ float d_c2 [BB * 64 * 1024];
static __device__ float d_ze [BB * TP * DD];
static __device__ float d_z  [BB * TP * DD];
static __device__ float d_xg [(size_t)BB * TP * G4];
static __device__ float d_h0 [(size_t)BB * TP * HH];
static __device__ float d_h1s[(size_t)BB * TP * HH];
static __device__ float d_hbuf[2 * HH * BB];     // [buf][b][j]
static __device__ int   d_flags[TP];

// ---------------- tokenizer ----------------
__global__ void k_mean(const float* __restrict__ x) {
    int idx = blockIdx.x * 256 + threadIdx.x;            // b*T + t
    const float4* xp = (const float4*)x + (size_t)idx * 16;
    float s = 0.f;
#pragma unroll
    for (int i = 0; i < 16; i++) { float4 v = xp[i]; s += v.x + v.y + v.z + v.w; }
    d_sig[idx] = s * (1.0f / 64.0f);
}

__global__ void k_conv1(const float* __restrict__ w1, const float* __restrict__ b1) {
    __shared__ float ws[256];
    __shared__ float bs[64];
    int tid = threadIdx.x;
    if (tid < 256) ws[tid] = w1[tid];
    if (tid < 64)  bs[tid] = b1[tid];
    __syncthreads();
    int b = blockIdx.y;
    int p = blockIdx.x * 256 + tid;
    const float* sg = d_sig + (size_t)b * TT;
    float in[4];
#pragma unroll
    for (int j = 0; j < 4; j++) {
        int q = 2 * p + j - 1;
        in[j] = (q >= 0 && q < TT) ? sg[q] : 0.f;
    }
    for (int o = 0; o < 64; o++) {
        float a = bs[o];
#pragma unroll
        for (int j = 0; j < 4; j++) a = fmaf(ws[o * 4 + j], in[j], a);
        d_c1[((size_t)(b * 64 + o)) * 2048 + p] = fmaxf(a, 0.f);
    }
}

__global__ void k_conv2(const float* __restrict__ w2, const float* __restrict__ b2) {
    extern __shared__ float sm2[];
    float* ws    = sm2;                 // 64*64*4
    float* patch = ws + 16384;          // 64*67
    float* bs    = patch + 64 * 67;
    int tid = threadIdx.x;
    for (int i = tid; i < 16384; i += 256) ws[i] = w2[i];
    if (tid < 64) bs[tid] = b2[tid];
    int b  = blockIdx.y;
    int p0 = blockIdx.x * 32;
    int q0 = 2 * p0 - 1;
    for (int i = tid; i < 64 * 67; i += 256) {
        int c = i / 67, dq = i % 67, q = q0 + dq;
        patch[i] = (q >= 0 && q < 2048) ? d_c1[((size_t)(b * 64 + c)) * 2048 + q] : 0.f;
    }
    __syncthreads();
    int po = tid & 31, og = tid >> 5;
    float acc[8];
#pragma unroll
    for (int i = 0; i < 8; i++) acc[i] = 0.f;
    for (int c = 0; c < 64; c++) {
        const float* pc = patch + c * 67 + 2 * po;
        float i0 = pc[0], i1 = pc[1], i2 = pc[2], i3 = pc[3];
#pragma unroll
        for (int oi = 0; oi < 8; oi++) {
            const float* wp = &ws[((og * 8 + oi) * 64 + c) * 4];
            acc[oi] = fmaf(wp[0], i0, fmaf(wp[1], i1, fmaf(wp[2], i2, fmaf(wp[3], i3, acc[oi]))));
        }
    }
#pragma unroll
    for (int oi = 0; oi < 8; oi++) {
        int o = og * 8 + oi;
        d_c2[((size_t)(b * 64 + o)) * 1024 + p0 + po] = fmaxf(acc[oi] + bs[o], 0.f);
    }
}

__global__ void k_conv3(const float* __restrict__ w3, const float* __restrict__ b3) {
    extern __shared__ float sm3[];
    float* ws    = sm3;                 // 64*64*3
    float* patch = ws + 12288;          // 64*34
    float* bs    = patch + 64 * 34;
    int tid = threadIdx.x;
    for (int i = tid; i < 12288; i += 256) ws[i] = w3[i];
    if (tid < 64) bs[tid] = b3[tid];
    int b  = blockIdx.y;
    int p0 = blockIdx.x * 32;
    int q0 = p0 - 1;
    for (int i = tid; i < 64 * 34; i += 256) {
        int c = i / 34, dq = i % 34, q = q0 + dq;
        patch[i] = (q >= 0 && q < 1024) ? d_c2[((size_t)(b * 64 + c)) * 1024 + q] : 0.f;
    }
    __syncthreads();
    int po = tid & 31, og = tid >> 5;
    float acc[8];
#pragma unroll
    for (int i = 0; i < 8; i++) acc[i] = 0.f;
    for (int c = 0; c < 64; c++) {
        const float* pc = patch + c * 34 + po;
        float i0 = pc[0], i1 = pc[1], i2 = pc[2];
#pragma unroll
        for (int oi = 0; oi < 8; oi++) {
            const float* wp = &ws[((og * 8 + oi) * 64 + c) * 3];
            acc[oi] = fmaf(wp[0], i0, fmaf(wp[1], i1, fmaf(wp[2], i2, acc[oi])));
        }
    }
#pragma unroll
    for (int oi = 0; oi < 8; oi++) {
        int d = og * 8 + oi;
        d_ze[((size_t)(b * TP) + p0 + po) * 64 + d] = acc[oi] + bs[d];
    }
}

__global__ void k_quant(const float* __restrict__ cb) {
    extern __shared__ float smq[];
    float* cbs = smq;            // 256*64
    float* cn  = smq + 16384;    // 256
    int tid = threadIdx.x;       // 128 threads
    for (int i = tid; i < 16384; i += 128) cbs[i] = cb[i];
    __syncthreads();
    for (int c = tid; c < 256; c += 128) {
        float s = 0.f;
        const float* cp = cbs + c * 64;
#pragma unroll
        for (int d = 0; d < 64; d++) s = fmaf(cp[d], cp[d], s);
        cn[c] = s;
    }
    __syncthreads();
    int g = blockIdx.x * 128 + tid;
    float4 zr[16];
    const float4* zp = (const float4*)d_ze + (size_t)g * 16;
    float szz = 0.f;
#pragma unroll
    for (int i = 0; i < 16; i++) {
        zr[i] = zp[i];
        szz += zr[i].x * zr[i].x + zr[i].y * zr[i].y + zr[i].z * zr[i].z + zr[i].w * zr[i].w;
    }
    float best = 3.0e38f; int bi = 0;
    for (int c = 0; c < 256; c++) {
        const float4* cp = (const float4*)cbs + c * 16;
        float dot = 0.f;
#pragma unroll
        for (int i = 0; i < 16; i++) {
            float4 w = cp[i];
            dot = fmaf(w.x, zr[i].x, fmaf(w.y, zr[i].y, fmaf(w.z, zr[i].z, fmaf(w.w, zr[i].w, dot))));
        }
        float dist = szz - 2.f * dot + cn[c];
        if (dist < best) { best = dist; bi = c; }
    }
    float4* zo = (float4*)d_z + (size_t)g * 16;
    const float4* cbest = (const float4*)cbs + bi * 16;
#pragma unroll
    for (int i = 0; i < 16; i++) zo[i] = cbest[i];
}

// ---------------- GEMM (f32x2): C[M,N] = A[M,K]*B[N,K]^T + bias[N] ----------------
// 128x128 tile, 256 threads, 16 rows x 4 cols per thread, row-pairs packed in f32x2.
__global__ void __launch_bounds__(256, 2) k_gemm2(
    const float* __restrict__ A, const float* __restrict__ B,
    const float* __restrict__ bias, float* __restrict__ C,
    int M, int N, int K)
{
    __shared__ float As[16][132];
    __shared__ float Bs[16][128];
    int tid = threadIdx.x;
    int bm = blockIdx.y << 7, bn = blockIdx.x << 7;
    int ty = tid >> 5, tx = tid & 31;

    unsigned long long acc[8][4];
#pragma unroll
    for (int p = 0; p < 8; p++)
#pragma unroll
        for (int j = 0; j < 4; j++) acc[p][j] = 0ULL;

    for (int k0 = 0; k0 < K; k0 += 16) {
        __syncthreads();
#pragma unroll
        for (int q = 0; q < 2; q++) {
            int i = tid * 2 + q;
            int r = i >> 2, c4 = (i & 3) << 2;
            float4 av = *(const float4*)(A + (size_t)(bm + r) * K + k0 + c4);
            As[c4 + 0][r] = av.x; As[c4 + 1][r] = av.y;
            As[c4 + 2][r] = av.z; As[c4 + 3][r] = av.w;
            float4 bv = *(const float4*)(B + (size_t)(bn + r) * K + k0 + c4);
            Bs[c4 + 0][r] = bv.x; Bs[c4 + 1][r] = bv.y;
            Bs[c4 + 2][r] = bv.z; Bs[c4 + 3][r] = bv.w;
        }
        __syncthreads();
#pragma unroll 4
        for (int k = 0; k < 16; k++) {
            const ulonglong2* ap = (const ulonglong2*)&As[k][ty << 4];
            ulonglong2 aA = ap[0], aB2 = ap[1], aC = ap[2], aD = ap[3];
            float4 b4 = *(const float4*)&Bs[k][tx << 2];
            unsigned long long d0 = pack2(b4.x, b4.x);
            unsigned long long d1 = pack2(b4.y, b4.y);
            unsigned long long d2 = pack2(b4.z, b4.z);
            unsigned long long d3 = pack2(b4.w, b4.w);
#define ROWF(p, P) \
            acc[p][0] = ffma2(P, d0, acc[p][0]); acc[p][1] = ffma2(P, d1, acc[p][1]); \
            acc[p][2] = ffma2(P, d2, acc[p][2]); acc[p][3] = ffma2(P, d3, acc[p][3]);
            ROWF(0, aA.x)  ROWF(1, aA.y)  ROWF(2, aB2.x) ROWF(3, aB2.y)
            ROWF(4, aC.x)  ROWF(5, aC.y)  ROWF(6, aD.x)  ROWF(7, aD.y)
#undef ROWF
        }
    }
    float b0 = bias[bn + (tx << 2) + 0];
    float b1 = bias[bn + (tx << 2) + 1];
    float b2 = bias[bn + (tx << 2) + 2];
    float b3 = bias[bn + (tx << 2) + 3];
#pragma unroll
    for (int p = 0; p < 8; p++) {
        float2 v0 = unpack2(acc[p][0]);
        float2 v1 = unpack2(acc[p][1]);
        float2 v2 = unpack2(acc[p][2]);
        float2 v3 = unpack2(acc[p][3]);
        int r0 = bm + (ty << 4) + (p << 1);
        float4 o0 = make_float4(v0.x + b0, v1.x + b1, v2.x + b2, v3.x + b3);
        float4 o1 = make_float4(v0.y + b0, v1.y + b1, v2.y + b2, v3.y + b3);
        *(float4*)(C + (size_t)r0 * N + bn + (tx << 2)) = o0;
        *(float4*)(C + (size_t)(r0 + 1) * N + bn + (tx << 2)) = o1;
    }
}

// ---------------- persistent LSTM ----------------
__global__ void k_lstm_init() {
    int i = blockIdx.x * 256 + threadIdx.x;
    if (i < TP) d_flags[i] = 0;
    if (i < HH * BB) d_hbuf[i] = 0.f;
}

// CTA owns 4 hidden units (16 gate rows, packed into 8 f32x2 row-pairs).
// h state [buf][b][j] in global; staged each step into smem hT[b][k] (pad 516).
__global__ void __launch_bounds__(256, 1) k_lstm(
    const float* __restrict__ xg,   // [B,T',4H]
    const float* __restrict__ whh,  // [4H,H]
    float* __restrict__ hseq)       // [B,T',H]
{
    extern __shared__ unsigned long long smx[];
    unsigned long long* whh_p = smx;                 // 8*512 f32x2
    float* hT   = (float*)(smx + 8 * HH);            // 32*516
    float* gbuf = hT + 32 * 516;                     // 4*16*32
    const int tid   = threadIdx.x;
    const int jbase = blockIdx.x * 4;

    // pack whh row pairs: pr = gate*2 + half -> rows (gate*4 + half*2, +1) of this CTA
#pragma unroll
    for (int pr = 0; pr < 8; pr++) {
        int gate = pr >> 1, half = pr & 1;
        const float* w0 = whh + (size_t)(gate * HH + jbase + half * 2) * HH;
        const float* w1 = w0 + HH;
        for (int k = tid; k < HH; k += 256)
            whh_p[pr * HH + k] = pack2(w0[k], w1[k]);
    }

    const int lane = tid & 31, wid = tid >> 5;
    const int prg  = (wid & 1) * 4;     // packed-row group: 0 or 4
    const int kq   = wid >> 1;          // k quarter 0..3
    const int k0   = kq * 128;
    const int gb   = tid >> 2, gu = tid & 3;
    float cst = 0.f;

    for (int t = 0; t < TP; t++) {
        // prefetch xg for this step (hidden under staging + matmul)
        float xv0 = 0.f, xv1 = 0.f, xv2 = 0.f, xv3 = 0.f;
        if (tid < 128) {
            const float* xp = xg + ((size_t)gb * TP + t) * G4 + jbase + gu;
            xv0 = __ldg(xp);        xv1 = __ldg(xp + 512);
            xv2 = __ldg(xp + 1024); xv3 = __ldg(xp + 1536);
        }
        // stage h_t: global [b][j] -> smem hT[b][k] (straight copy, L2-only loads)
        const float4* hg = (const float4*)(d_hbuf + (size_t)(t & 1) * (HH * BB));
#pragma unroll
        for (int it = 0; it < 16; it++) {
            int i = tid + it * 256;
            float4 v = __ldcg(hg + i);
            *(float4*)&hT[(i >> 7) * 516 + ((i & 127) << 2)] = v;
        }
        __syncthreads();
        // matmul: 4 packed row-pairs x 128 k per warp, f32x2
        {
            unsigned long long a0 = 0ULL, a1 = 0ULL, a2 = 0ULL, a3 = 0ULL;
            const float* hp = hT + lane * 516 + k0;
            const unsigned long long* wb = whh_p + k0;
#pragma unroll 2
            for (int kk = 0; kk < 128; kk += 4) {
                float4 hv = *(const float4*)(hp + kk);
                unsigned long long h0 = pack2(hv.x, hv.x);
                unsigned long long h1 = pack2(hv.y, hv.y);
                unsigned long long h2 = pack2(hv.z, hv.z);
                unsigned long long h3 = pack2(hv.w, hv.w);
#define STEPP(p, accv) { \
                const ulonglong2* wp_ = (const ulonglong2*)(wb + (prg + p) * HH + kk); \
                ulonglong2 wa = wp_[0], wc = wp_[1]; \
                accv = ffma2(wa.x, h0, accv); accv = ffma2(wa.y, h1, accv); \
                accv = ffma2(wc.x, h2, accv); accv = ffma2(wc.y, h3, accv); }
                STEPP(0, a0) STEPP(1, a1) STEPP(2, a2) STEPP(3, a3)
#undef STEPP
            }
#define WRB(p, accv) { \
            float2 g = unpack2(accv); \
            int row = (((prg + p) >> 1) << 2) + (((prg + p) & 1) << 1); \
            gbuf[(kq * 16 + row) * 32 + lane]     = g.x; \
            gbuf[(kq * 16 + row + 1) * 32 + lane] = g.y; }
            WRB(0, a0) WRB(1, a1) WRB(2, a2) WRB(3, a3)
#undef WRB
        }
        __syncthreads();
        // gates: 128 threads (b = tid>>2, u = tid&3)
        if (tid < 128) {
            const int b = gb, u = gu, j = jbase + u;
            float gi = xv0, gf = xv1, gg = xv2, go = xv3;
#pragma unroll
            for (int q = 0; q < 4; q++) {
                const float* gp = gbuf + (q * 16 + u) * 32 + b;
                gi += gp[0];
                gf += gp[4 * 32];
                gg += gp[8 * 32];
                go += gp[12 * 32];
            }
            float iv = fsigmoid(gi);
            float fv = fsigmoid(gf);
            float gv = ftanh(gg);
            float ov = fsigmoid(go);
            cst = fmaf(fv, cst, iv * gv);
            float hv = ov * ftanh(cst);
            d_hbuf[(size_t)((t + 1) & 1) * (HH * BB) + b * HH + j] = hv;
            hseq[((size_t)b * TP + t) * HH + j] = hv;
        }
        if (t < TP - 1) {
            __threadfence();
            __syncthreads();
            if (tid == 0) {
                atomicAdd(&d_flags[t], 1);
                while (((volatile int*)d_flags)[t] < NCTA) { }
            }
            __syncthreads();
        }
    }
}

// ---------------- head ----------------
__global__ void k_head(const float* __restrict__ wout, const float* __restrict__ bout,
                       const float* __restrict__ hs, float* __restrict__ out)
{
    __shared__ float ws[OUTD * HH];
    __shared__ float bs[OUTD];
    int tid = threadIdx.x;
    for (int i = tid; i < OUTD * HH; i += 256) ws[i] = wout[i];
    if (tid < OUTD) bs[tid] = bout[tid];
    __syncthreads();
    int warp = tid >> 5, lane = tid & 31;
    int g = blockIdx.x * 8 + warp;       // b*T' + t
    const float4* hp = (const float4*)(hs + (size_t)g * HH);
    float4 hv[4];
#pragma unroll
    for (int c = 0; c < 4; c++) hv[c] = hp[lane + 32 * c];
#pragma unroll
    for (int o = 0; o < OUTD; o++) {
        const float4* wp = (const float4*)(ws + o * HH);
        float s = 0.f;
#pragma unroll
        for (int c = 0; c < 4; c++) {
            float4 w = wp[lane + 32 * c];
            s = fmaf(w.x, hv[c].x, fmaf(w.y, hv[c].y, fmaf(w.z, hv[c].z, fmaf(w.w, hv[c].w, s))));
        }
#pragma unroll
        for (int off = 16; off; off >>= 1) s += __shfl_xor_sync(0xFFFFFFFFu, s, off);
        if (lane == 0) out[(size_t)g * OUTD + o] = s + bs[o];
    }
}

// ---------------- launch ----------------
extern "C" void kernel_launch(void* const* d_in, const int* in_sizes, int n_in,
                              void* d_out, int out_size) {
    (void)in_sizes; (void)n_in; (void)out_size;
    const float* x     = (const float*)d_in[0];
    const float* cw1   = (const float*)d_in[1];
    const float* cb1   = (const float*)d_in[2];
    const float* cw2   = (const float*)d_in[3];
    const float* cb2   = (const float*)d_in[4];
    const float* cw3   = (const float*)d_in[5];
    const float* cb3   = (const float*)d_in[6];
    const float* cbook = (const float*)d_in[7];
    const float* wih0  = (const float*)d_in[8];
    const float* whh0  = (const float*)d_in[9];
    const float* bl0   = (const float*)d_in[10];
    const float* wih1  = (const float*)d_in[11];
    const float* whh1  = (const float*)d_in[12];
    const float* bl1   = (const float*)d_in[13];
    const float* wout  = (const float*)d_in[14];
    const float* bout  = (const float*)d_in[15];
    float* out = (float*)d_out;

    const int smem_conv2 = (16384 + 64 * 67 + 64) * 4;
    const int smem_conv3 = (12288 + 64 * 34 + 64) * 4;
    const int smem_quant = (16384 + 256) * 4;
    const int smem_lstm  = 8 * HH * 8 + 32 * 516 * 4 + 4 * 16 * 32 * 4;  // 107008

    static float *pz = nullptr, *pxg = nullptr, *ph0 = nullptr, *ph1s = nullptr;
    if (!pz) {
        cudaGetSymbolAddress((void**)&pz,   d_z);
        cudaGetSymbolAddress((void**)&pxg,  d_xg);
        cudaGetSymbolAddress((void**)&ph0,  d_h0);
        cudaGetSymbolAddress((void**)&ph1s, d_h1s);
        cudaFuncSetAttribute(k_conv2, cudaFuncAttributeMaxDynamicSharedMemorySize, smem_conv2);
        cudaFuncSetAttribute(k_conv3, cudaFuncAttributeMaxDynamicSharedMemorySize, smem_conv3);
        cudaFuncSetAttribute(k_quant, cudaFuncAttributeMaxDynamicSharedMemorySize, smem_quant);
        cudaFuncSetAttribute(k_lstm,  cudaFuncAttributeMaxDynamicSharedMemorySize, smem_lstm);
    }

    // tokenizer
    k_mean <<<(BB * TT) / 256, 256>>>(x);
    k_conv1<<<dim3(8, BB), 256>>>(cw1, cb1);
    k_conv2<<<dim3(32, BB), 256, smem_conv2>>>(cw2, cb2);
    k_conv3<<<dim3(32, BB), 256, smem_conv3>>>(cw3, cb3);
    k_quant<<<(BB * TP) / 128, 128, smem_quant>>>(cbook);

    // layer 0
    k_gemm2<<<dim3(G4 / 128, (BB * TP) / 128), 256>>>(pz, wih0, bl0, pxg, BB * TP, G4, DD);
    k_lstm_init<<<64, 256>>>();
    k_lstm<<<NCTA, 256, smem_lstm>>>(pxg, whh0, ph0);

    // layer 1
    k_gemm2<<<dim3(G4 / 128, (BB * TP) / 128), 256>>>(ph0, wih1, bl1, pxg, BB * TP, G4, HH);
    k_lstm_init<<<64, 256>>>();
    k_lstm<<<NCTA, 256, smem_lstm>>>(pxg, whh1, ph1s);

    // head
    k_head<<<(BB * TP) / 8, 256>>>(wout, bout, ph1s, out);
}

// round 13
// speedup vs baseline: 1.1708x; 1.1708x over previous
#include <cuda_runtime.h>
#include <math.h>
#include <stdint.h>
#include <stddef.h>

#define BB   32
#define TT   4096
#define TP   1024
#define DD   64
#define HH   512
#define G4   2048
#define OUTD 6
#define NCTA 128

typedef unsigned long long ULL;
__device__ __forceinline__ ULL ffma2(ULL a, ULL b, ULL c) {
    ULL d; asm("fma.rn.f32x2 %0, %1, %2, %3;" : "=l"(d) : "l"(a), "l"(b), "l"(c)); return d;
}
__device__ __forceinline__ ULL pack2(float lo, float hi) {
    ULL r; asm("mov.b64 %0, {%1, %2};" : "=l"(r) : "f"(lo), "f"(hi)); return r;
}
__device__ __forceinline__ float2 unpack2(ULL v) {
    float2 r; asm("mov.b64 {%0, %1}, %2;" : "=f"(r.x), "=f"(r.y) : "l"(v)); return r;
}
__device__ __forceinline__ float fsigmoid(float x) { return __fdividef(1.f, 1.f + __expf(-x)); }
__device__ __forceinline__ float ftanh(float x) { return 1.f - __fdividef(2.f, __expf(2.f * x) + 1.f); }
__device__ __forceinline__ int ldflag(const int* p) {
    int v; asm volatile("ld.global.cg.b32 %0, [%1];" : "=r"(v) : "l"(p) : "memory"); return v;
}
__device__ __forceinline__ void stflag(int* p, int v) {
    asm volatile("st.global.cg.b32 [%0], %1;" :: "l"(p), "r"(v) : "memory");
}

// ---------------- scratch ----------------
static __device__ float d_sig[BB * TT];
static __device__ float d_c1 [BB * 64 * 2048];
static __device__ float d_c2 [BB * 64 * 1024];
static __device__ float d_ze [BB * TP * DD];
static __device__ float d_z  [BB * TP * DD];
static __device__ float d_xg [(size_t)BB * TP * G4];
static __device__ float d_h1s[(size_t)BB * TP * HH];
static __device__ float d_hcat[2 * 1024 * BB];   // [slot][kk][b]; kk<512 h0, >=512 h1
static __device__ int   d_flags2[NCTA];

// ---------------- tokenizer ----------------
__global__ void k_mean(const float* __restrict__ x) {
    int idx = blockIdx.x * 256 + threadIdx.x;
    const float4* xp = (const float4*)x + (size_t)idx * 16;
    float s = 0.f;
#pragma unroll
    for (int i = 0; i < 16; i++) { float4 v = xp[i]; s += v.x + v.y + v.z + v.w; }
    d_sig[idx] = s * (1.0f / 64.0f);
}

__global__ void k_conv1(const float* __restrict__ w1, const float* __restrict__ b1) {
    __shared__ float ws[256], bs[64];
    int tid = threadIdx.x;
    if (tid < 256) ws[tid] = w1[tid];
    if (tid < 64)  bs[tid] = b1[tid];
    __syncthreads();
    int b = blockIdx.y, p = blockIdx.x * 256 + tid;
    const float* sg = d_sig + (size_t)b * TT;
    float in[4];
#pragma unroll
    for (int j = 0; j < 4; j++) {
        int q = 2 * p + j - 1;
        in[j] = (q >= 0 && q < TT) ? sg[q] : 0.f;
    }
    for (int o = 0; o < 64; o++) {
        float a = bs[o];
#pragma unroll
        for (int j = 0; j < 4; j++) a = fmaf(ws[o * 4 + j], in[j], a);
        d_c1[((size_t)(b * 64 + o)) * 2048 + p] = fmaxf(a, 0.f);
    }
}

// templated conv: KS taps, stride STR, input length LIN; CL: channel-last output
template<int KS, int STR, int LIN, bool CL>
__global__ void k_conv(const float* __restrict__ src, const float* __restrict__ w,
                       const float* __restrict__ b, float* __restrict__ dst) {
    const int PW = 32 * STR + KS - 1;
    extern __shared__ float sm[];
    float* ws    = sm;                   // 64*64*KS
    float* patch = ws + 4096 * KS;       // 64*PW
    float* bs    = patch + 64 * PW;
    int tid = threadIdx.x;
    for (int i = tid; i < 4096 * KS; i += 256) ws[i] = w[i];
    if (tid < 64) bs[tid] = b[tid];
    int bb = blockIdx.y, p0 = blockIdx.x * 32, q0 = STR * p0 - 1;
    for (int i = tid; i < 64 * PW; i += 256) {
        int c = i / PW, q = q0 + i % PW;
        patch[i] = (q >= 0 && q < LIN) ? src[((size_t)(bb * 64 + c)) * LIN + q] : 0.f;
    }
    __syncthreads();
    int po = tid & 31, og = tid >> 5;
    float acc[8];
#pragma unroll
    for (int i = 0; i < 8; i++) acc[i] = 0.f;
    for (int c = 0; c < 64; c++) {
        const float* pc = patch + c * PW + STR * po;
        float iv[KS];
#pragma unroll
        for (int j = 0; j < KS; j++) iv[j] = pc[j];
#pragma unroll
        for (int oi = 0; oi < 8; oi++) {
            const float* wp = &ws[((og * 8 + oi) * 64 + c) * KS];
#pragma unroll
            for (int j = 0; j < KS; j++) acc[oi] = fmaf(wp[j], iv[j], acc[oi]);
        }
    }
#pragma unroll
    for (int oi = 0; oi < 8; oi++) {
        int o = og * 8 + oi;
        float v = acc[oi] + bs[o];
        if (CL) dst[((size_t)(bb * TP) + p0 + po) * 64 + o] = v;
        else    dst[((size_t)(bb * 64 + o)) * (LIN / STR) + p0 + po] = fmaxf(v, 0.f);
    }
}

__global__ void k_quant(const float* __restrict__ cb) {
    extern __shared__ float smq[];
    float* cbs = smq;            // 256*64
    float* cn  = smq + 16384;    // 256
    int tid = threadIdx.x;       // 128
    for (int i = tid; i < 16384; i += 128) cbs[i] = cb[i];
    __syncthreads();
    for (int c = tid; c < 256; c += 128) {
        float s = 0.f;
        const float* cp = cbs + c * 64;
#pragma unroll
        for (int d = 0; d < 64; d++) s = fmaf(cp[d], cp[d], s);
        cn[c] = s;
    }
    __syncthreads();
    int g = blockIdx.x * 128 + tid;
    float4 zr[16];
    const float4* zp = (const float4*)d_ze + (size_t)g * 16;
    float szz = 0.f;
#pragma unroll
    for (int i = 0; i < 16; i++) {
        zr[i] = zp[i];
        szz += zr[i].x * zr[i].x + zr[i].y * zr[i].y + zr[i].z * zr[i].z + zr[i].w * zr[i].w;
    }
    float best = 3.0e38f; int bi = 0;
    for (int c = 0; c < 256; c++) {
        const float4* cp = (const float4*)cbs + c * 16;
        float dot = 0.f;
#pragma unroll
        for (int i = 0; i < 16; i++) {
            float4 w = cp[i];
            dot = fmaf(w.x, zr[i].x, fmaf(w.y, zr[i].y, fmaf(w.z, zr[i].z, fmaf(w.w, zr[i].w, dot))));
        }
        float dist = szz - 2.f * dot + cn[c];
        if (dist < best) { best = dist; bi = c; }
    }
    float4* zo = (float4*)d_z + (size_t)g * 16;
    const float4* cbest = (const float4*)cbs + bi * 16;
#pragma unroll
    for (int i = 0; i < 16; i++) zo[i] = cbest[i];
}

// ---------------- GEMM (f32x2): C = A[M,K]*B[N,K]^T + bias ----------------
__global__ void __launch_bounds__(256, 2) k_gemm2(
    const float* __restrict__ A, const float* __restrict__ B,
    const float* __restrict__ bias, float* __restrict__ C, int M, int N, int K)
{
    __shared__ float As[16][132];
    __shared__ float Bs[16][128];
    int tid = threadIdx.x;
    int bm = blockIdx.y << 7, bn = blockIdx.x << 7;
    int ty = tid >> 5, tx = tid & 31;
    ULL acc[8][4];
#pragma unroll
    for (int p = 0; p < 8; p++)
#pragma unroll
        for (int j = 0; j < 4; j++) acc[p][j] = 0ULL;
    for (int k0 = 0; k0 < K; k0 += 16) {
        __syncthreads();
#pragma unroll
        for (int q = 0; q < 2; q++) {
            int i = tid * 2 + q, r = i >> 2, c4 = (i & 3) << 2;
            float4 av = *(const float4*)(A + (size_t)(bm + r) * K + k0 + c4);
            As[c4 + 0][r] = av.x; As[c4 + 1][r] = av.y; As[c4 + 2][r] = av.z; As[c4 + 3][r] = av.w;
            float4 bv = *(const float4*)(B + (size_t)(bn + r) * K + k0 + c4);
            Bs[c4 + 0][r] = bv.x; Bs[c4 + 1][r] = bv.y; Bs[c4 + 2][r] = bv.z; Bs[c4 + 3][r] = bv.w;
        }
        __syncthreads();
#pragma unroll 4
        for (int k = 0; k < 16; k++) {
            const ulonglong2* ap = (const ulonglong2*)&As[k][ty << 4];
            ulonglong2 aA = ap[0], aB2 = ap[1], aC = ap[2], aD = ap[3];
            float4 b4 = *(const float4*)&Bs[k][tx << 2];
            ULL d0 = pack2(b4.x, b4.x), d1 = pack2(b4.y, b4.y);
            ULL d2 = pack2(b4.z, b4.z), d3 = pack2(b4.w, b4.w);
#define ROWF(p, P) \
            acc[p][0] = ffma2(P, d0, acc[p][0]); acc[p][1] = ffma2(P, d1, acc[p][1]); \
            acc[p][2] = ffma2(P, d2, acc[p][2]); acc[p][3] = ffma2(P, d3, acc[p][3]);
            ROWF(0, aA.x)  ROWF(1, aA.y)  ROWF(2, aB2.x) ROWF(3, aB2.y)
            ROWF(4, aC.x)  ROWF(5, aC.y)  ROWF(6, aD.x)  ROWF(7, aD.y)
#undef ROWF
        }
    }
    float b0 = bias[bn + (tx << 2)], b1 = bias[bn + (tx << 2) + 1];
    float b2 = bias[bn + (tx << 2) + 2], b3 = bias[bn + (tx << 2) + 3];
#pragma unroll
    for (int p = 0; p < 8; p++) {
        float2 v0 = unpack2(acc[p][0]), v1 = unpack2(acc[p][1]);
        float2 v2 = unpack2(acc[p][2]), v3 = unpack2(acc[p][3]);
        int r0 = bm + (ty << 4) + (p << 1);
        *(float4*)(C + (size_t)r0 * N + bn + (tx << 2)) = make_float4(v0.x + b0, v1.x + b1, v2.x + b2, v3.x + b3);
        *(float4*)(C + (size_t)(r0 + 1) * N + bn + (tx << 2)) = make_float4(v0.y + b0, v1.y + b1, v2.y + b2, v3.y + b3);
    }
}

// ---------------- init ----------------
__global__ void k_init() {
    int i = blockIdx.x * 256 + threadIdx.x;
    if (i < 2 * 1024 * BB) d_hcat[i] = 0.f;
    if (i < NCTA) d_flags2[i] = 0;
}

// ---------------- fused 2-layer persistent LSTM ----------------
// 128 CTAs; CTA owns 4 units of both layers. Epoch e: L0 -> h0_e, L1 -> h1_{e-1}.
// Warp w: k-slice [w*128, w*128+128) of concat dim (w<4: h0; w>=4: h1).
// Weights in smem (f32x2 row-pairs): [0,4096) whh0, [4096,12288) [wih1|whh1].
__global__ void __launch_bounds__(256, 1) k_fused(
    const float* __restrict__ xg, const float* __restrict__ whh0,
    const float* __restrict__ wih1, const float* __restrict__ whh1,
    const float* __restrict__ bl1, float* __restrict__ h1s)
{
    extern __shared__ ULL smw[];
    float* gbufA = (float*)(smw + 12288);   // 4 slices * 16 * 32
    float* gbufB = gbufA + 2048;            // 8 slices * 16 * 32
    const int tid = threadIdx.x, cta = blockIdx.x, jbase = cta * 4;
    const int lane = tid & 31, wid = tid >> 5;

    for (int i = tid; i < 4096; i += 256) {          // L0 weights
        int w = i >> 10, p = (i >> 7) & 7, kk = w * 128 + (i & 127);
        const float* s0 = whh0 + (size_t)((p >> 1) * HH + jbase + (p & 1) * 2) * HH + kk;
        smw[i] = pack2(s0[0], s0[HH]);
    }
    for (int i = tid; i < 8192; i += 256) {          // L1 concat weights
        int w = i >> 10, p = (i >> 7) & 7, kk = w * 128 + (i & 127);
        int r0 = (p >> 1) * HH + jbase + (p & 1) * 2;
        const float* s0 = (kk < HH) ? (wih1 + (size_t)r0 * HH + kk)
                                    : (whh1 + (size_t)r0 * HH + kk - HH);
        smw[4096 + i] = pack2(s0[0], s0[HH]);
    }
    __syncthreads();

    const ULL* w0p = smw + wid * 1024;
    const ULL* w1p = smw + 4096 + wid * 1024;
    const bool heavy = wid < 4;
    float c0 = 0.f, c1 = 0.f, bv0 = 0.f, bv1 = 0.f, bv2 = 0.f, bv3 = 0.f;
    if (tid < 128) {
        int j = jbase + wid;                 // gate thread: unit=wid(0..3), batch=lane
        bv0 = bl1[j]; bv1 = bl1[HH + j]; bv2 = bl1[2 * HH + j]; bv3 = bl1[3 * HH + j];
    }

    for (int e = 0; e <= TP; e++) {
        const int slot = e & 1;
        float xv0 = 0.f, xv1 = 0.f, xv2 = 0.f, xv3 = 0.f;
        if (tid < 128 && e < TP) {
            const float* xp = xg + ((size_t)lane * TP + e) * G4 + jbase + wid;
            xv0 = __ldg(xp); xv1 = __ldg(xp + HH); xv2 = __ldg(xp + 2 * HH); xv3 = __ldg(xp + 3 * HH);
        }
        if (e > 0 && tid < NCTA) {
            while (ldflag(&d_flags2[tid]) < e) __nanosleep(32);
        }
        __syncthreads();

        {   // matvec over own k-slice; h read straight from L2 ([kk][b] coalesced)
            const float* hp = d_hcat + slot * 32768 + wid * 4096 + lane;
            ULL B0=0,B1=0,B2=0,B3=0,B4=0,B5=0,B6=0,B7=0;
#define WSTEP(wp, p, A) { ulonglong2 u0 = *(const ulonglong2*)((wp) + (p)*128 + kc); \
            ulonglong2 u1 = *(const ulonglong2*)((wp) + (p)*128 + kc + 2); \
            A = ffma2(u0.x, q0, A); A = ffma2(u0.y, q1, A); \
            A = ffma2(u1.x, q2, A); A = ffma2(u1.y, q3, A); }
            if (heavy) {
                ULL A0=0,A1=0,A2=0,A3=0,A4=0,A5=0,A6=0,A7=0;
#pragma unroll 2
                for (int kc = 0; kc < 128; kc += 4) {
                    float h0 = __ldcg(hp + kc * 32),       h1 = __ldcg(hp + (kc + 1) * 32);
                    float h2 = __ldcg(hp + (kc + 2) * 32), h3 = __ldcg(hp + (kc + 3) * 32);
                    ULL q0 = pack2(h0, h0), q1 = pack2(h1, h1), q2 = pack2(h2, h2), q3 = pack2(h3, h3);
                    WSTEP(w0p,0,A0) WSTEP(w0p,1,A1) WSTEP(w0p,2,A2) WSTEP(w0p,3,A3)
                    WSTEP(w0p,4,A4) WSTEP(w0p,5,A5) WSTEP(w0p,6,A6) WSTEP(w0p,7,A7)
                    WSTEP(w1p,0,B0) WSTEP(w1p,1,B1) WSTEP(w1p,2,B2) WSTEP(w1p,3,B3)
                    WSTEP(w1p,4,B4) WSTEP(w1p,5,B5) WSTEP(w1p,6,B6) WSTEP(w1p,7,B7)
                }
#define WRA(p, A) { float2 v = unpack2(A); int o = ((wid * 4 + ((p) >> 1)) * 4 + ((p) & 1) * 2) * 32 + lane; \
                gbufA[o] = v.x; gbufA[o + 32] = v.y; }
                WRA(0,A0) WRA(1,A1) WRA(2,A2) WRA(3,A3) WRA(4,A4) WRA(5,A5) WRA(6,A6) WRA(7,A7)
#undef WRA
            } else {
#pragma unroll 2
                for (int kc = 0; kc < 128; kc += 4) {
                    float h0 = __ldcg(hp + kc * 32),       h1 = __ldcg(hp + (kc + 1) * 32);
                    float h2 = __ldcg(hp + (kc + 2) * 32), h3 = __ldcg(hp + (kc + 3) * 32);
                    ULL q0 = pack2(h0, h0), q1 = pack2(h1, h1), q2 = pack2(h2, h2), q3 = pack2(h3, h3);
                    WSTEP(w1p,0,B0) WSTEP(w1p,1,B1) WSTEP(w1p,2,B2) WSTEP(w1p,3,B3)
                    WSTEP(w1p,4,B4) WSTEP(w1p,5,B5) WSTEP(w1p,6,B6) WSTEP(w1p,7,B7)
                }
            }
#define WRB(p, A) { float2 v = unpack2(A); int o = ((wid * 4 + ((p) >> 1)) * 4 + ((p) & 1) * 2) * 32 + lane; \
            gbufB[o] = v.x; gbufB[o + 32] = v.y; }
            WRB(0,B0) WRB(1,B1) WRB(2,B2) WRB(3,B3) WRB(4,B4) WRB(5,B5) WRB(6,B6) WRB(7,B7)
#undef WRB
#undef WSTEP
        }
        __syncthreads();

        if (tid < 128) {
            const int u = wid, b = lane;
            if (e < TP) {   // layer 0 cell, time e
                float g0 = xv0, g1 = xv1, g2 = xv2, g3 = xv3;
#pragma unroll
                for (int s = 0; s < 4; s++) {
                    const float* q = gbufA + (s * 16 + u) * 32 + b;
                    g0 += q[0]; g1 += q[128]; g2 += q[256]; g3 += q[384];
                }
                float iv = fsigmoid(g0), fv = fsigmoid(g1), gg = ftanh(g2), ov = fsigmoid(g3);
                c0 = fmaf(fv, c0, iv * gg);
                d_hcat[(slot ^ 1) * 32768 + (jbase + u) * 32 + b] = ov * ftanh(c0);
            }
            if (e >= 1) {   // layer 1 cell, time e-1
                float g0 = bv0, g1 = bv1, g2 = bv2, g3 = bv3;
#pragma unroll
                for (int s = 0; s < 8; s++) {
                    const float* q = gbufB + (s * 16 + u) * 32 + b;
                    g0 += q[0]; g1 += q[128]; g2 += q[256]; g3 += q[384];
                }
                float iv = fsigmoid(g0), fv = fsigmoid(g1), gg = ftanh(g2), ov = fsigmoid(g3);
                c1 = fmaf(fv, c1, iv * gg);
                float hv = ov * ftanh(c1);
                d_hcat[(slot ^ 1) * 32768 + (512 + jbase + u) * 32 + b] = hv;
                h1s[((size_t)b * TP + e - 1) * HH + jbase + u] = hv;
            }
        }
        if (e < TP) {
            __threadfence();
            __syncthreads();
            if (tid == 0) stflag(&d_flags2[cta], e + 1);
        }
    }
}

// ---------------- head ----------------
__global__ void k_head(const float* __restrict__ wout, const float* __restrict__ bout,
                       const float* __restrict__ hs, float* __restrict__ out)
{
    __shared__ float ws[OUTD * HH];
    __shared__ float bs[OUTD];
    int tid = threadIdx.x;
    for (int i = tid; i < OUTD * HH; i += 256) ws[i] = wout[i];
    if (tid < OUTD) bs[tid] = bout[tid];
    __syncthreads();
    int warp = tid >> 5, lane = tid & 31;
    int g = blockIdx.x * 8 + warp;
    const float4* hp = (const float4*)(hs + (size_t)g * HH);
    float4 hv[4];
#pragma unroll
    for (int c = 0; c < 4; c++) hv[c] = hp[lane + 32 * c];
#pragma unroll
    for (int o = 0; o < OUTD; o++) {
        const float4* wp = (const float4*)(ws + o * HH);
        float s = 0.f;
#pragma unroll
        for (int c = 0; c < 4; c++) {
            float4 w = wp[lane + 32 * c];
            s = fmaf(w.x, hv[c].x, fmaf(w.y, hv[c].y, fmaf(w.z, hv[c].z, fmaf(w.w, hv[c].w, s))));
        }
#pragma unroll
        for (int off = 16; off; off >>= 1) s += __shfl_xor_sync(0xFFFFFFFFu, s, off);
        if (lane == 0) out[(size_t)g * OUTD + o] = s + bs[o];
    }
}

// ---------------- launch ----------------
extern "C" void kernel_launch(void* const* d_in, const int* in_sizes, int n_in,
                              void* d_out, int out_size) {
    (void)in_sizes; (void)n_in; (void)out_size;
    const float* x    = (const float*)d_in[0];
    const float* cw1  = (const float*)d_in[1];
    const float* cb1  = (const float*)d_in[2];
    const float* cw2  = (const float*)d_in[3];
    const float* cb2  = (const float*)d_in[4];
    const float* cw3  = (const float*)d_in[5];
    const float* cb3  = (const float*)d_in[6];
    const float* cbk  = (const float*)d_in[7];
    const float* wih0 = (const float*)d_in[8];
    const float* whh0 = (const float*)d_in[9];
    const float* bl0  = (const float*)d_in[10];
    const float* wih1 = (const float*)d_in[11];
    const float* whh1 = (const float*)d_in[12];
    const float* bl1  = (const float*)d_in[13];
    const float* wout = (const float*)d_in[14];
    const float* bout = (const float*)d_in[15];
    float* out = (float*)d_out;

    const int smem_c2 = (16384 + 64 * 67 + 64) * 4;
    const int smem_c3 = (12288 + 64 * 34 + 64) * 4;
    const int smem_q  = (16384 + 256) * 4;
    const int smem_f  = 12288 * 8 + 6144 * 4;   // 122880

    static float *pc1 = nullptr, *pc2, *pz, *pxg, *ph1s;
    if (!pc1) {
        cudaGetSymbolAddress((void**)&pc1,  d_c1);
        cudaGetSymbolAddress((void**)&pc2,  d_c2);
        cudaGetSymbolAddress((void**)&pz,   d_z);
        cudaGetSymbolAddress((void**)&pxg,  d_xg);
        cudaGetSymbolAddress((void**)&ph1s, d_h1s);
        cudaFuncSetAttribute((const void*)k_conv<4,2,2048,false>, cudaFuncAttributeMaxDynamicSharedMemorySize, smem_c2);
        cudaFuncSetAttribute((const void*)k_conv<3,1,1024,true>,  cudaFuncAttributeMaxDynamicSharedMemorySize, smem_c3);
        cudaFuncSetAttribute((const void*)k_quant, cudaFuncAttributeMaxDynamicSharedMemorySize, smem_q);
        cudaFuncSetAttribute((const void*)k_fused, cudaFuncAttributeMaxDynamicSharedMemorySize, smem_f);
    }

    k_mean <<<(BB * TT) / 256, 256>>>(x);
    k_conv1<<<dim3(8, BB), 256>>>(cw1, cb1);
    k_conv<4,2,2048,false><<<dim3(32, BB), 256, smem_c2>>>(pc1, cw2, cb2, pc2);
    float* pze; cudaGetSymbolAddress((void**)&pze, d_ze);
    k_conv<3,1,1024,true><<<dim3(32, BB), 256, smem_c3>>>(pc2, cw3, cb3, pze);
    k_quant<<<(BB * TP) / 128, 128, smem_q>>>(cbk);

    k_gemm2<<<dim3(G4 / 128, (BB * TP) / 128), 256>>>(pz, wih0, bl0, pxg, BB * TP, G4, DD);
    k_init<<<256, 256>>>();
    k_fused<<<NCTA, 256, smem_f>>>(pxg, whh0, wih1, whh1, bl1, ph1s);

    k_head<<<(BB * TP) / 8, 256>>>(wout, bout, ph1s, out);
}